// round 2
// baseline (speedup 1.0000x reference)
#include <cuda_runtime.h>
#include <math.h>

// Problem constants
constexpr int B    = 8;
constexpr int CIN  = 32;
constexpr int H    = 24;
constexpr int COUT = 64;
constexpr int KS   = 5;
constexpr int HO   = 20;              // (24-5)+1
constexpr int L    = HO * HO;         // 400
constexpr int D    = CIN * KS * KS;   // 800
constexpr int MU_Z_ELEMS = B * COUT * L;   // 204800

// Scratch (device globals; no allocations allowed)
__device__ float g_A[B * L * D];            // mu patches [b][l][d]      (10.24 MB)
__device__ float g_diagS[B * CIN * H * H];  // diag of sigma as [b,c,h,w]
__device__ float g_WT[D * COUT];            // W transposed: [d][o]
__device__ float g_sp[COUT];                // softplus(sigma_weight)
__device__ float g_mmT[2][B * L * L];       // K-split partials of A A^T (10.24 MB)
__device__ float g_diagAdd[B * COUT * L];   // mu_w + sp*trace

// ---------------------------------------------------------------------------
// Kernel 1: prep — build patches, diag(sigma), W^T, softplus
// ---------------------------------------------------------------------------
__global__ void k_prep(const float* __restrict__ mu,
                       const float* __restrict__ sigma,
                       const float* __restrict__ W,
                       const float* __restrict__ sw) {
    int i = blockIdx.x * blockDim.x + threadIdx.x;

    if (i < COUT) {
        g_sp[i] = log1pf(expf(sw[i]));
    }

    if (i < B * L * D) {
        int b = i / (L * D);
        int r = i % (L * D);
        int l = r / D;
        int d = r % D;
        int c  = d / (KS * KS);
        int rr = d % (KS * KS);
        int kh = rr / KS;
        int kw = rr % KS;
        int oh = l / HO;
        int ow = l % HO;
        g_A[i] = mu[((b * CIN + c) * H + oh + kh) * H + ow + kw];
        return;
    }

    int j = i - B * L * D;
    if (j < B * CIN * H * H) {
        int p  = j % (H * H);
        int bc = j / (H * H);
        // sigma: [B, CIN, 576, 576], diagonal element p
        g_diagS[j] = sigma[(long long)bc * (576LL * 576LL) + (long long)p * 577LL];
        return;
    }

    int t = j - B * CIN * H * H;
    if (t < D * COUT) {
        int d = t / COUT;
        int o = t % COUT;
        g_WT[t] = W[o * D + d];   // true transpose for the conv path
    }
}

// ---------------------------------------------------------------------------
// Kernel 2: diag path — per (b,l): mu_w[o] + sp[o]*trace
// mu_w uses the reference's faithful flat reshape: wsq[d][o] = (W_flat[d*64+o])^2
// ---------------------------------------------------------------------------
__global__ void k_diagpath(const float* __restrict__ W) {
    __shared__ float s[D];
    __shared__ float s_tr[2];

    int bl = blockIdx.x;                // 0 .. B*L-1
    int b  = bl / L;
    int l  = bl % L;
    int oh = l / HO;
    int ow = l % HO;
    int tid = threadIdx.x;              // 0..63

    for (int d = tid; d < D; d += 64) {
        int c  = d / (KS * KS);
        int rr = d % (KS * KS);
        int kh = rr / KS;
        int kw = rr % KS;
        s[d] = g_diagS[((b * CIN + c) * H + oh + kh) * H + ow + kw];
    }
    __syncthreads();

    // trace = sum_d s[d]
    float tp = 0.f;
    for (int d = tid; d < D; d += 64) tp += s[d];
    #pragma unroll
    for (int off = 16; off; off >>= 1) tp += __shfl_xor_sync(0xffffffffu, tp, off);
    if ((tid & 31) == 0) s_tr[tid >> 5] = tp;
    __syncthreads();
    float trace = s_tr[0] + s_tr[1];

    int o = tid;
    float acc = 0.f;
    #pragma unroll 4
    for (int d = 0; d < D; d++) {
        float w = W[d * COUT + o];      // flat index d*64+o into W (faithful reshape)
        acc = fmaf(s[d] * w, w, acc);
    }
    g_diagAdd[(b * COUT + o) * L + l] = acc + g_sp[o] * trace;
}

// ---------------------------------------------------------------------------
// Kernel 3: symmetric GEMM  C_b = A_b * A_b^T, 64x64 tiles, triangular + K-split
// grid = B * 28 * 2 CTAs, 256 threads, 4x4 microtile per thread.
// ---------------------------------------------------------------------------
__global__ void __launch_bounds__(256) k_gemm() {
    __shared__ float As[64][37];
    __shared__ float Bs[64][37];

    int cta = blockIdx.x;
    int kh  = cta & 1;
    int bt  = cta >> 1;            // 0..223
    int b   = bt / 28;
    int t   = bt % 28;
    int ti  = 0;
    while (t >= 7 - ti) { t -= 7 - ti; ti++; }
    int tj = ti + t;               // ti <= tj, tiles of 64 over 400 (7 tiles)

    int I = ti * 64;
    int J = tj * 64;
    int k0base = kh ? 416 : 0;     // 416 = 13*32, 384 = 12*32 (no K guards)
    int ksteps = kh ? 12 : 13;

    int tid = threadIdx.x;
    int ty  = tid >> 4;            // 0..15
    int tx  = tid & 15;            // 0..15
    int i0  = ty * 4;
    int j0  = tx * 4;

    float acc[4][4] = {};
    const float* Abase = g_A + (long long)b * L * D;

    for (int s = 0; s < ksteps; s++) {
        int k0 = k0base + s * 32;
        #pragma unroll
        for (int q = 0; q < 2; q++) {
            int f   = tid + q * 256;
            int row = f >> 3;          // 0..63
            int c4  = (f & 7) * 4;     // 0..28
            int col = k0 + c4;

            int gr = I + row;
            float4 va = make_float4(0.f, 0.f, 0.f, 0.f);
            if (gr < L) va = *(const float4*)(Abase + (long long)gr * D + col);
            As[row][c4 + 0] = va.x; As[row][c4 + 1] = va.y;
            As[row][c4 + 2] = va.z; As[row][c4 + 3] = va.w;

            int gs = J + row;
            float4 vb = make_float4(0.f, 0.f, 0.f, 0.f);
            if (gs < L) vb = *(const float4*)(Abase + (long long)gs * D + col);
            Bs[row][c4 + 0] = vb.x; Bs[row][c4 + 1] = vb.y;
            Bs[row][c4 + 2] = vb.z; Bs[row][c4 + 3] = vb.w;
        }
        __syncthreads();

        #pragma unroll 8
        for (int k = 0; k < 32; k++) {
            float a0 = As[i0 + 0][k], a1 = As[i0 + 1][k];
            float a2 = As[i0 + 2][k], a3 = As[i0 + 3][k];
            float b0 = Bs[j0 + 0][k], b1 = Bs[j0 + 1][k];
            float b2 = Bs[j0 + 2][k], b3 = Bs[j0 + 3][k];
            acc[0][0] = fmaf(a0, b0, acc[0][0]); acc[0][1] = fmaf(a0, b1, acc[0][1]);
            acc[0][2] = fmaf(a0, b2, acc[0][2]); acc[0][3] = fmaf(a0, b3, acc[0][3]);
            acc[1][0] = fmaf(a1, b0, acc[1][0]); acc[1][1] = fmaf(a1, b1, acc[1][1]);
            acc[1][2] = fmaf(a1, b2, acc[1][2]); acc[1][3] = fmaf(a1, b3, acc[1][3]);
            acc[2][0] = fmaf(a2, b0, acc[2][0]); acc[2][1] = fmaf(a2, b1, acc[2][1]);
            acc[2][2] = fmaf(a2, b2, acc[2][2]); acc[2][3] = fmaf(a2, b3, acc[2][3]);
            acc[3][0] = fmaf(a3, b0, acc[3][0]); acc[3][1] = fmaf(a3, b1, acc[3][1]);
            acc[3][2] = fmaf(a3, b2, acc[3][2]); acc[3][3] = fmaf(a3, b3, acc[3][3]);
        }
        __syncthreads();
    }

    float* gm = &g_mmT[kh][(long long)b * L * L];
    #pragma unroll
    for (int u = 0; u < 4; u++) {
        int gi = I + i0 + u;
        if (gi >= L) continue;
        #pragma unroll
        for (int v = 0; v < 4; v++) {
            int gj = J + j0 + v;
            if (gj >= L) continue;
            float c = acc[u][v];
            gm[gi * L + gj] = c;
            if (ti != tj) gm[gj * L + gi] = c;   // mirror (C symmetric)
        }
    }
}

// ---------------------------------------------------------------------------
// Kernel 4: mean conv  mu_z[b,o,l] = sum_d A[b,l,d] * W[o,d]
// ---------------------------------------------------------------------------
__global__ void k_mu(float* __restrict__ out) {
    __shared__ float s[D];
    int bl = blockIdx.x;
    int b  = bl / L;
    int l  = bl % L;
    int tid = threadIdx.x;

    const float* arow = &g_A[((long long)b * L + l) * D];
    for (int d = tid; d < D; d += 64) s[d] = arow[d];
    __syncthreads();

    int o = tid;
    float acc = 0.f;
    #pragma unroll 4
    for (int d = 0; d < D; d++) acc = fmaf(s[d], g_WT[d * COUT + o], acc);
    out[(b * COUT + o) * L + l] = acc;
}

// ---------------------------------------------------------------------------
// Kernel 5: broadcast writer — sigma_z[b,o,l,m] = sp[o]*mmT[b,l,m] (+diag add)
// one thread per (b, l, 4 columns of m); 64 streaming float4 stores.
// Diagonal contribution handled branch-free via a 0/1 lane selector.
// ---------------------------------------------------------------------------
__global__ void __launch_bounds__(256) k_write(float* __restrict__ out) {
    __shared__ float ssp[COUT];
    if (threadIdx.x < COUT) ssp[threadIdx.x] = g_sp[threadIdx.x];
    __syncthreads();

    int gid = blockIdx.x * blockDim.x + threadIdx.x;
    if (gid >= B * L * (L / 4)) return;

    int b  = gid / (L * (L / 4));
    int r  = gid % (L * (L / 4));
    int l  = r / (L / 4);
    int m4 = r % (L / 4);
    int m  = m4 * 4;

    long long x = ((long long)b * L + l) * L + m;
    float4 p0 = *(const float4*)&g_mmT[0][x];
    float4 p1 = *(const float4*)&g_mmT[1][x];
    float v0 = p0.x + p1.x, v1 = p0.y + p1.y;
    float v2 = p0.z + p1.z, v3 = p0.w + p1.w;

    int  dl = l - m;                   // which lane holds the diagonal (if any)
    float s0 = (dl == 0) ? 1.f : 0.f;
    float s1 = (dl == 1) ? 1.f : 0.f;
    float s2 = (dl == 2) ? 1.f : 0.f;
    float s3 = (dl == 3) ? 1.f : 0.f;
    bool hasd = (dl >= 0 && dl < 4);
    const float* dptr = &g_diagAdd[(b * COUT) * L + l];

    float* outp = out + MU_Z_ELEMS + (((long long)b * COUT) * L + l) * L + m;

    #pragma unroll 4
    for (int o = 0; o < COUT; o++) {
        float sp = ssp[o];
        float a  = hasd ? dptr[o * L] : 0.f;
        float r0 = fmaf(sp, v0, s0 * a);
        float r1 = fmaf(sp, v1, s1 * a);
        float r2 = fmaf(sp, v2, s2 * a);
        float r3 = fmaf(sp, v3, s3 * a);
        __stcs((float4*)outp, make_float4(r0, r1, r2, r3));
        outp += (long long)L * L;
    }
}

// ---------------------------------------------------------------------------
extern "C" void kernel_launch(void* const* d_in, const int* in_sizes, int n_in,
                              void* d_out, int out_size) {
    const float* mu    = (const float*)d_in[0];
    const float* sigma = (const float*)d_in[1];
    const float* W     = (const float*)d_in[2];
    const float* sw    = (const float*)d_in[3];
    float* out = (float*)d_out;

    int prep_total = B * L * D + B * CIN * H * H + D * COUT;
    k_prep<<<(prep_total + 255) / 256, 256>>>(mu, sigma, W, sw);
    k_diagpath<<<B * L, 64>>>(W);
    k_gemm<<<B * 28 * 2, 256>>>();
    k_mu<<<B * L, 64>>>(out);
    k_write<<<(B * L * (L / 4) + 255) / 256, 256>>>(out);
}

// round 7
// speedup vs baseline: 1.2994x; 1.2994x over previous
#include <cuda_runtime.h>
#include <math.h>

// Problem constants
constexpr int B    = 8;
constexpr int CIN  = 32;
constexpr int H    = 24;
constexpr int COUT = 64;
constexpr int KS   = 5;
constexpr int HO   = 20;              // (24-5)+1
constexpr int L    = HO * HO;         // 400
constexpr int D    = CIN * KS * KS;   // 800
constexpr int MU_Z_ELEMS = B * COUT * L;   // 204800
constexpr int TL   = 7;               // ceil(400/64) tiles along L

// Scratch (device globals; no allocations allowed)
__device__ float g_A[B * L * D];            // mu patches [b][l][d]      (10.24 MB)
__device__ float g_DS[B * L * D];           // diag-sigma patches        (10.24 MB)
__device__ float g_diagS[B * CIN * H * H];  // diag of sigma as [b,c,h,w]
__device__ float g_WT[D * COUT];            // W transposed: [d][o]
__device__ float g_sp[COUT];                // softplus(sigma_weight)
__device__ float g_trace[B * L];            // sum_d DS[b,l,d]
__device__ float g_dadd[B * COUT * L];      // mu_w + sp*trace  [b][o][l]

// ---------------------------------------------------------------------------
// Kernel 1: prep — mu patches, diag(sigma), W^T, softplus
// ---------------------------------------------------------------------------
__global__ void k_prep(const float* __restrict__ mu,
                       const float* __restrict__ sigma,
                       const float* __restrict__ W,
                       const float* __restrict__ sw) {
    int i = blockIdx.x * blockDim.x + threadIdx.x;

    if (i < COUT) g_sp[i] = log1pf(expf(sw[i]));

    if (i < B * L * D) {
        int b = i / (L * D);
        int r = i % (L * D);
        int l = r / D;
        int d = r % D;
        int c  = d / (KS * KS);
        int rr = d % (KS * KS);
        int kh = rr / KS;
        int kw = rr % KS;
        int oh = l / HO;
        int ow = l % HO;
        g_A[i] = mu[((b * CIN + c) * H + oh + kh) * H + ow + kw];
        return;
    }

    int j = i - B * L * D;
    if (j < B * CIN * H * H) {
        int p  = j % (H * H);
        int bc = j / (H * H);
        g_diagS[j] = sigma[(long long)bc * (576LL * 576LL) + (long long)p * 577LL];
        return;
    }

    int t = j - B * CIN * H * H;
    if (t < D * COUT) {
        int d = t / COUT;
        int o = t % COUT;
        g_WT[t] = W[o * D + d];
    }
}

// ---------------------------------------------------------------------------
// Kernel 2: diag-sigma patches (needs g_diagS complete)
// ---------------------------------------------------------------------------
__global__ void k_prep2() {
    int i = blockIdx.x * blockDim.x + threadIdx.x;
    if (i >= B * L * D) return;
    int b = i / (L * D);
    int r = i % (L * D);
    int l = r / D;
    int d = r % D;
    int c  = d / (KS * KS);
    int rr = d % (KS * KS);
    int kh = rr / KS;
    int kw = rr % KS;
    int oh = l / HO;
    int ow = l % HO;
    g_DS[i] = g_diagS[((b * CIN + c) * H + oh + kh) * H + ow + kw];
}

// ---------------------------------------------------------------------------
// Kernel 3: trace[b,l] = sum_d DS[b,l,d]  (one warp per row)
// ---------------------------------------------------------------------------
__global__ void k_trace() {
    int w    = (blockIdx.x * blockDim.x + threadIdx.x) >> 5;
    int lane = threadIdx.x & 31;
    if (w >= B * L) return;
    const float* rowp = g_DS + (long long)w * D;
    float s = 0.f;
    #pragma unroll 5
    for (int d = lane; d < D; d += 32) s += rowp[d];
    #pragma unroll
    for (int off = 16; off; off >>= 1) s += __shfl_xor_sync(0xffffffffu, s, off);
    if (lane == 0) g_trace[w] = s;
}

// ---------------------------------------------------------------------------
// Kernel 4: small GEMMs  [400x800]x[800x64] per b
//   mode 0: mu_z[b,o,l]  = sum_d A[b,l,d]  * WT[d,o]          -> out
//   mode 1: dadd[b,o,l]  = sum_d DS[b,l,d] * W_flat[d*64+o]^2 + sp[o]*trace
// grid = 2*B*7 = 112 CTAs, 256 threads, 64(l)x64(o) tile, 4x4 microtile.
// ---------------------------------------------------------------------------
__global__ void __launch_bounds__(256) k_small(const float* __restrict__ W,
                                               float* __restrict__ out) {
    __shared__ __align__(16) float As[32][68];   // k-major: As[k][row(l)]
    __shared__ __align__(16) float Bs[32][68];   // k-major: Bs[k][o]

    int cta  = blockIdx.x;
    int mode = cta / (B * TL);
    int r    = cta % (B * TL);
    int b    = r / TL;
    int ti   = r % TL;
    int I    = ti * 64;

    int tid = threadIdx.x;
    int ty  = tid >> 4, tx = tid & 15;
    int i0  = ty * 4,  j0 = tx * 4;

    const float* Ab = (mode ? g_DS : g_A) + (long long)b * L * D;

    float acc[4][4] = {};

    for (int s = 0; s < 25; s++) {
        int k0 = s * 32;
        // load A tile (transpose into k-major)
        #pragma unroll
        for (int q = 0; q < 2; q++) {
            int f   = tid + q * 256;
            int row = f >> 3;          // 0..63
            int cc  = (f & 7) * 4;     // 0..28
            int gr  = I + row;
            float4 va = make_float4(0.f, 0.f, 0.f, 0.f);
            if (gr < L) va = *(const float4*)(Ab + (long long)gr * D + k0 + cc);
            As[cc + 0][row] = va.x; As[cc + 1][row] = va.y;
            As[cc + 2][row] = va.z; As[cc + 3][row] = va.w;
        }
        // load B tile (already k-major in memory)
        #pragma unroll
        for (int q = 0; q < 2; q++) {
            int f  = tid + q * 256;
            int kr = f >> 4;           // 0..31
            int o4 = (f & 15) * 4;     // 0..60
            float4 w;
            if (mode == 0) {
                w = *(const float4*)&g_WT[(k0 + kr) * COUT + o4];
            } else {
                w = *(const float4*)&W[(k0 + kr) * COUT + o4];  // flat [800][64]
                w.x *= w.x; w.y *= w.y; w.z *= w.z; w.w *= w.w;
            }
            *(float4*)&Bs[kr][o4] = w;
        }
        __syncthreads();

        #pragma unroll
        for (int k = 0; k < 32; k++) {
            float4 av = *(const float4*)&As[k][i0];
            float4 bv = *(const float4*)&Bs[k][j0];
            float a[4] = {av.x, av.y, av.z, av.w};
            float c[4] = {bv.x, bv.y, bv.z, bv.w};
            #pragma unroll
            for (int u = 0; u < 4; u++)
                #pragma unroll
                for (int v = 0; v < 4; v++)
                    acc[u][v] = fmaf(a[u], c[v], acc[u][v]);
        }
        __syncthreads();
    }

    // epilogue: store column-v as float4 over u (l consecutive)
    int gi0 = I + i0;
    if (gi0 >= L) return;   // rows 400..443 out of range (mult-of-4 aligned)

    if (mode == 0) {
        #pragma unroll
        for (int v = 0; v < 4; v++) {
            int o = j0 + v;
            float4 rv = make_float4(acc[0][v], acc[1][v], acc[2][v], acc[3][v]);
            *(float4*)&out[((long long)b * COUT + o) * L + gi0] = rv;
        }
    } else {
        float4 tr = *(const float4*)&g_trace[b * L + gi0];
        float t4[4] = {tr.x, tr.y, tr.z, tr.w};
        #pragma unroll
        for (int v = 0; v < 4; v++) {
            int o = j0 + v;
            float sp = g_sp[o];
            float4 rv = make_float4(fmaf(sp, t4[0], acc[0][v]),
                                    fmaf(sp, t4[1], acc[1][v]),
                                    fmaf(sp, t4[2], acc[2][v]),
                                    fmaf(sp, t4[3], acc[3][v]));
            *(float4*)&g_dadd[((long long)b * COUT + o) * L + gi0] = rv;
        }
    }
}

// ---------------------------------------------------------------------------
// Kernel 5: fused A*A^T GEMM + broadcast scaled write of sigma_z
// grid = B*49, 256 threads. Each CTA: full-K 64x64 tile of mmT, then writes
// 64 scaled copies (one per cout) with diagonal add folded in.
// ---------------------------------------------------------------------------
__global__ void __launch_bounds__(256) k_fused(float* __restrict__ out) {
    __shared__ __align__(16) float As[32][68];   // k-major
    __shared__ __align__(16) float Bs[32][68];
    __shared__ float ssp[COUT];

    int cta = blockIdx.x;
    int b   = cta / (TL * TL);
    int t   = cta % (TL * TL);
    int ti  = t / TL;
    int tj  = t % TL;
    int I   = ti * 64;
    int J   = tj * 64;

    int tid = threadIdx.x;
    int ty  = tid >> 4, tx = tid & 15;
    int i0  = ty * 4,  j0 = tx * 4;

    if (tid < COUT) ssp[tid] = g_sp[tid];

    const float* Ab = g_A + (long long)b * L * D;
    float acc[4][4] = {};

    for (int s = 0; s < 25; s++) {
        int k0 = s * 32;
        #pragma unroll
        for (int q = 0; q < 2; q++) {
            int f   = tid + q * 256;
            int row = f >> 3;
            int cc  = (f & 7) * 4;

            int gr = I + row;
            float4 va = make_float4(0.f, 0.f, 0.f, 0.f);
            if (gr < L) va = *(const float4*)(Ab + (long long)gr * D + k0 + cc);
            As[cc + 0][row] = va.x; As[cc + 1][row] = va.y;
            As[cc + 2][row] = va.z; As[cc + 3][row] = va.w;

            int gs = J + row;
            float4 vb = make_float4(0.f, 0.f, 0.f, 0.f);
            if (gs < L) vb = *(const float4*)(Ab + (long long)gs * D + k0 + cc);
            Bs[cc + 0][row] = vb.x; Bs[cc + 1][row] = vb.y;
            Bs[cc + 2][row] = vb.z; Bs[cc + 3][row] = vb.w;
        }
        __syncthreads();

        #pragma unroll
        for (int k = 0; k < 32; k++) {
            float4 av = *(const float4*)&As[k][i0];
            float4 bv = *(const float4*)&Bs[k][j0];
            float a[4] = {av.x, av.y, av.z, av.w};
            float c[4] = {bv.x, bv.y, bv.z, bv.w};
            #pragma unroll
            for (int u = 0; u < 4; u++)
                #pragma unroll
                for (int v = 0; v < 4; v++)
                    acc[u][v] = fmaf(a[u], c[v], acc[u][v]);
        }
        __syncthreads();
    }

    int gi0 = I + i0;
    int gj0 = J + j0;
    bool okJ    = (gj0 < L);             // float4 fully in-range (L mult of 4)
    bool okI0   = (gi0 < L);
    bool isdiag = (ti == tj) && (ty == tx) && okI0;

    if (!okJ || !okI0) return;           // nothing to store for this thread

    float* base = out + MU_Z_ELEMS
                + (((long long)b * COUT) * L + gi0) * (long long)L + gj0;
    const float* dbase = &g_dadd[((long long)b * COUT) * L + gi0];

    #pragma unroll 2
    for (int o = 0; o < COUT; o++) {
        float sp = ssp[o];
        float4 dv = make_float4(0.f, 0.f, 0.f, 0.f);
        if (isdiag) dv = *(const float4*)(dbase + (long long)o * L);
        float d4[4] = {dv.x, dv.y, dv.z, dv.w};

        #pragma unroll
        for (int u = 0; u < 4; u++) {
            float4 rv;
            rv.x = fmaf(sp, acc[u][0], (u == 0) ? d4[0] : 0.f);
            rv.y = fmaf(sp, acc[u][1], (u == 1) ? d4[1] : 0.f);
            rv.z = fmaf(sp, acc[u][2], (u == 2) ? d4[2] : 0.f);
            rv.w = fmaf(sp, acc[u][3], (u == 3) ? d4[3] : 0.f);
            __stcs((float4*)(base + (long long)u * L), rv);
        }
        base += (long long)L * L;
    }
}

// ---------------------------------------------------------------------------
extern "C" void kernel_launch(void* const* d_in, const int* in_sizes, int n_in,
                              void* d_out, int out_size) {
    const float* mu    = (const float*)d_in[0];
    const float* sigma = (const float*)d_in[1];
    const float* W     = (const float*)d_in[2];
    const float* sw    = (const float*)d_in[3];
    float* out = (float*)d_out;

    int prep_total = B * L * D + B * CIN * H * H + D * COUT;
    k_prep<<<(prep_total + 255) / 256, 256>>>(mu, sigma, W, sw);
    k_prep2<<<(B * L * D + 255) / 256, 256>>>();
    k_trace<<<(B * L * 32 + 255) / 256, 256>>>();
    k_small<<<2 * B * TL, 256>>>(W, out);
    k_fused<<<B * TL * TL, 256>>>(out);
}